// round 15
// baseline (speedup 1.0000x reference)
#include <cuda_runtime.h>
#include <cuda_bf16.h>
#include <cstdint>
#include <math.h>

#define DIMX 4096
#define SEQT 1024
#define NB 2
#define NHEADS 32
#define HD 128
#define NQKV 3072          // reduced qkv width: 1024 qred + 1024 K + 1024 V
#define NATT 1024          // reduced attention output width
#define KSPLIT 3

__device__ float g_qkv[(size_t)NB * SEQT * NQKV];
__device__ float g_att[(size_t)NB * SEQT * NATT];
__device__ float g_xr [(size_t)NB * SEQT * DIMX];
__device__ float g_w1p[(size_t)NQKV * DIMX];
__device__ float g_w2p[(size_t)DIMX * NATT];
__device__ float g_b1p[NQKV];
__device__ float g_part[(size_t)KSPLIT * NB * SEQT * NQKV];

// ---------------------------------------------------------------------------
__device__ __forceinline__ uint32_t smem_u32(const void* p) {
    uint32_t a;
    asm("{ .reg .u64 t; cvta.to.shared.u64 t, %1; cvt.u32.u64 %0, t; }" : "=r"(a) : "l"(p));
    return a;
}
__device__ __forceinline__ float f2tf32f(float f) {
    uint32_t u;
    asm("cvt.rna.tf32.f32 %0, %1;" : "=r"(u) : "f"(f));
    return __uint_as_float(u);
}
__device__ __forceinline__ void cp16(uint32_t dst, const void* src) {
    asm volatile("cp.async.cg.shared.global [%0], [%1], 16;" :: "r"(dst), "l"(src));
}
#define CP_COMMIT() asm volatile("cp.async.commit_group;" ::: "memory")
#define CP_WAIT(n)  asm volatile("cp.async.wait_group %0;" :: "n"(n) : "memory")

__device__ __forceinline__ void mma_tf32(float* d, const uint32_t* a, const uint32_t* b) {
    asm volatile(
        "mma.sync.aligned.m16n8k8.row.col.f32.tf32.tf32.f32 "
        "{%0,%1,%2,%3}, {%4,%5,%6,%7}, {%8,%9}, {%0,%1,%2,%3};"
        : "+f"(d[0]), "+f"(d[1]), "+f"(d[2]), "+f"(d[3])
        : "r"(a[0]), "r"(a[1]), "r"(a[2]), "r"(a[3]), "r"(b[0]), "r"(b[1]));
}

__device__ __forceinline__ int k8pos(int c) { return (c < 4) ? 2 * c : 2 * (c - 4) + 1; }

// ---------------------------------------------------------------------------
__global__ void round_perm(const float* __restrict__ in, float* __restrict__ out, int n8) {
    int i = blockIdx.x * blockDim.x + threadIdx.x;
    if (i < n8) {
        float4 a = ((const float4*)in)[2 * i];
        float4 b = ((const float4*)in)[2 * i + 1];
        float4 o0, o1;
        o0.x = f2tf32f(a.x); o0.y = f2tf32f(b.x);
        o0.z = f2tf32f(a.y); o0.w = f2tf32f(b.y);
        o1.x = f2tf32f(a.z); o1.y = f2tf32f(b.z);
        o1.z = f2tf32f(a.w); o1.w = f2tf32f(b.w);
        ((float4*)out)[2 * i]     = o0;
        ((float4*)out)[2 * i + 1] = o1;
    }
}

// ---------------------------------------------------------------------------
__global__ void prep_w1(const float* __restrict__ W1, const float* __restrict__ b1,
                        float* __restrict__ W1p, float* __restrict__ b1p) {
    const float scale = 0.08838834764831845f;
    int idx = blockIdx.x * blockDim.x + threadIdx.x;
    if (idx >= NQKV * (DIMX / 8)) return;
    int row = idx / (DIMX / 8);
    int grp = idx % (DIMX / 8);

    float v[8];
    if (row < 1024) {
        const float* s0 = W1 + (size_t)(4 * row) * DIMX + grp * 8;
        #pragma unroll
        for (int c = 0; c < 8; c++)
            v[c] = scale * (s0[c] + s0[DIMX + c] + s0[2 * DIMX + c] + s0[3 * DIMX + c]);
        if (grp == 0)
            b1p[row] = scale * (b1[4 * row] + b1[4 * row + 1] + b1[4 * row + 2] + b1[4 * row + 3]);
    } else {
        int src = (row < 2048) ? (4096 + row - 1024) : (5120 + row - 2048);
        const float* s0 = W1 + (size_t)src * DIMX + grp * 8;
        #pragma unroll
        for (int c = 0; c < 8; c++) v[c] = s0[c];
        if (grp == 0) b1p[row] = b1[src];
    }
    float* o = W1p + (size_t)row * DIMX + grp * 8;
    #pragma unroll
    for (int c = 0; c < 8; c++) o[k8pos(c)] = f2tf32f(v[c]);
}

// ---------------------------------------------------------------------------
__global__ void prep_w2(const float* __restrict__ W2, float* __restrict__ W2p) {
    int idx = blockIdx.x * blockDim.x + threadIdx.x;
    if (idx >= DIMX * (NATT / 8)) return;
    int n   = idx / (NATT / 8);
    int grp = idx % (NATT / 8);
    const float* s0 = W2 + (size_t)n * DIMX + grp * 32;
    float* o = W2p + (size_t)n * NATT + grp * 8;
    #pragma unroll
    for (int c = 0; c < 8; c++) {
        float v = s0[4 * c] + s0[4 * c + 1] + s0[4 * c + 2] + s0[4 * c + 3];
        o[k8pos(c)] = f2tf32f(v);
    }
}

// ---------------------------------------------------------------------------
__global__ void reduce_k(const float* __restrict__ part, const float* __restrict__ bias,
                         float* __restrict__ out, int n4, int stride_elems) {
    int i = blockIdx.x * blockDim.x + threadIdx.x;
    if (i >= n4) return;
    float4 p0 = ((const float4*)part)[i];
    float4 p1 = ((const float4*)(part + (size_t)stride_elems))[i];
    float4 p2 = ((const float4*)(part + 2 * (size_t)stride_elems))[i];
    int col = (i * 4) % NQKV;
    float4 bv = *(const float4*)(bias + col);
    float4 o;
    o.x = (p0.x + p1.x + p2.x) + bv.x;
    o.y = (p0.y + p1.y + p2.y) + bv.y;
    o.z = (p0.z + p1.z + p2.z) + bv.z;
    o.w = (p0.w + p1.w + p2.w) + bv.w;
    ((float4*)out)[i] = o;
}

// ---------------------------------------------------------------------------
// tf32 mma.sync GEMM (R14 verbatim) with split-K via blockIdx.z.
// ---------------------------------------------------------------------------
#define APAD 40
#define TILE_F (128 * APAD)
#define STAGE_F (2 * TILE_F)
#define GEMM_SMEM (2 * STAGE_F * 4)        // 81920 B

__global__ __launch_bounds__(128, 2)
void tf32_gemm(const float* __restrict__ A, const float* __restrict__ W,
               const float* __restrict__ bias, float* __restrict__ C,
               int N, int K) {
    extern __shared__ float sm[];

    const int tid  = threadIdx.x;
    const int wid  = tid / 32;
    const int lane = tid % 32;
    const int wm   = wid >> 1;
    const int wn   = wid & 1;
    const int g    = lane >> 2;
    const int t    = lane & 3;
    const int bx   = blockIdx.x;
    const int by   = blockIdx.y;
    const int bz   = blockIdx.z;

    const int ktot  = K / 32;
    const int kper  = (ktot + (int)gridDim.z - 1) / (int)gridDim.z;
    const int kbeg  = bz * kper;
    const int ntiles = min(kper, ktot - kbeg);

    float* Cz = C + (size_t)bz * (size_t)(gridDim.y * 128) * N;

    const float* Ab = A + (size_t)(by * 128) * K + (size_t)kbeg * 32;
    const float* Wb = W + (size_t)(bx * 128) * K + (size_t)kbeg * 32;

    float acc[4][8][4];
    #pragma unroll
    for (int i = 0; i < 4; i++)
        #pragma unroll
        for (int j = 0; j < 8; j++)
            #pragma unroll
            for (int c = 0; c < 4; c++) acc[i][j][c] = 0.0f;

    const int crow = tid >> 3;
    const int ckc  = (tid & 7) * 4;

    auto load_tile = [&](int buf, int kt) {
        float* as = sm + buf * STAGE_F;
        float* bs = as + TILE_F;
        uint32_t as_u = smem_u32(as);
        uint32_t bs_u = smem_u32(bs);
        const float* Asrc = Ab + kt * 32;
        const float* Bsrc = Wb + kt * 32;
        #pragma unroll
        for (int i = 0; i < 8; i++) {
            int row = crow + i * 16;
            uint32_t doff = (uint32_t)(row * APAD + ckc) * 4u;
            cp16(as_u + doff, Asrc + (size_t)row * K + ckc);
            cp16(bs_u + doff, Bsrc + (size_t)row * K + ckc);
        }
        CP_COMMIT();
    };

    load_tile(0, 0);
    if (ntiles > 1) load_tile(1, 1);

    for (int kt = 0; kt < ntiles; kt++) {
        CP_WAIT(1);
        __syncthreads();

        const int buf = kt & 1;
        const float* as = sm + buf * STAGE_F + (wm * 64) * APAD;
        const float* bs = sm + buf * STAGE_F + TILE_F + (wn * 64) * APAD;

        #pragma unroll
        for (int ks = 0; ks < 4; ks++) {
            const int k0 = ks * 8 + 2 * t;
            uint32_t af[4][4], bf[8][2];
            #pragma unroll
            for (int mt = 0; mt < 4; mt++) {
                float2 lo = *(const float2*)(as + (mt * 16 + g) * APAD + k0);
                float2 hi = *(const float2*)(as + (mt * 16 + g + 8) * APAD + k0);
                af[mt][0] = __float_as_uint(lo.x);
                af[mt][1] = __float_as_uint(hi.x);
                af[mt][2] = __float_as_uint(lo.y);
                af[mt][3] = __float_as_uint(hi.y);
            }
            #pragma unroll
            for (int nt = 0; nt < 8; nt++) {
                float2 bb = *(const float2*)(bs + (nt * 8 + g) * APAD + k0);
                bf[nt][0] = __float_as_uint(bb.x);
                bf[nt][1] = __float_as_uint(bb.y);
            }
            #pragma unroll
            for (int mt = 0; mt < 4; mt++)
                #pragma unroll
                for (int nt = 0; nt < 8; nt++)
                    mma_tf32(acc[mt][nt], af[mt], bf[nt]);
        }

        __syncthreads();
        if (kt + 2 < ntiles)
            load_tile(buf, kt + 2);
    }

    #pragma unroll
    for (int nt = 0; nt < 8; nt++) {
        const int col = bx * 128 + wn * 64 + nt * 8 + 2 * t;
        float2 bv = bias ? *(const float2*)(bias + col) : make_float2(0.f, 0.f);
        #pragma unroll
        for (int mt = 0; mt < 4; mt++) {
            const int row = by * 128 + wm * 64 + mt * 16 + g;
            float2 r0, r1;
            r0.x = acc[mt][nt][0] + bv.x;
            r0.y = acc[mt][nt][1] + bv.y;
            r1.x = acc[mt][nt][2] + bv.x;
            r1.y = acc[mt][nt][3] + bv.y;
            *(float2*)(Cz + (size_t)row * N + col)       = r0;
            *(float2*)(Cz + (size_t)(row + 8) * N + col) = r1;
        }
    }
}

// ---------------------------------------------------------------------------
// Flash attention — R14 arithmetic VERBATIM. Only changes:
//   * __launch_bounds__(256, 4): 32 warps/SM to hide shfl/LDS latency
//   * qt reversed (long blocks launch first -> better tail packing)
// ---------------------------------------------------------------------------
__global__ __launch_bounds__(256, 4)
void attn_kernel(const float* __restrict__ qkv, float* __restrict__ out) {
    __shared__ float Qs[32][32];
    __shared__ float Kt[32][33];
    __shared__ float Vs[32][32];

    const int qt   = (int)gridDim.x - 1 - (int)blockIdx.x;   // long blocks first
    const int h    = blockIdx.y;
    const int b    = blockIdx.z;
    const int tid  = threadIdx.x;
    const int wid  = tid / 32;
    const int lane = tid % 32;

    const float* base = qkv + (size_t)b * SEQT * NQKV;

    #pragma unroll
    for (int it = 0; it < 4; it++) {
        int r = it * 8 + wid;
        Qs[r][lane] = base[(size_t)(qt * 32 + r) * NQKV + h * 32 + lane];
    }

    float ov[4] = {0.f, 0.f, 0.f, 0.f};
    float m[4] = {-1e30f, -1e30f, -1e30f, -1e30f};
    float l[4] = {0.f, 0.f, 0.f, 0.f};
    const int qr0 = qt * 32 + wid * 4;

    const int ntiles = qt + 1;

    for (int tt = 0; tt < ntiles; tt++) {
        __syncthreads();
        {
            int r  = tid / 8;
            int d4 = (tid % 8) * 4;
            const float* rowp = base + (size_t)(tt * 32 + r) * NQKV + 1024 + h * 32 + d4;
            float4 kk = *(const float4*)(rowp);
            float4 vv = *(const float4*)(rowp + 1024);
            Kt[d4 + 0][r] = kk.x; Kt[d4 + 1][r] = kk.y;
            Kt[d4 + 2][r] = kk.z; Kt[d4 + 3][r] = kk.w;
            *(float4*)(&Vs[r][d4]) = vv;
        }
        __syncthreads();

        const int kg = tt * 32 + lane;
        const float* q0 = Qs[wid * 4 + 0];
        const float* q1 = Qs[wid * 4 + 1];
        const float* q2 = Qs[wid * 4 + 2];
        const float* q3 = Qs[wid * 4 + 3];

        float s[4] = {0.f, 0.f, 0.f, 0.f};
        #pragma unroll
        for (int j = 0; j < 32; j++) {
            float kv = Kt[j][lane];
            s[0] = fmaf(q0[j], kv, s[0]);
            s[1] = fmaf(q1[j], kv, s[1]);
            s[2] = fmaf(q2[j], kv, s[2]);
            s[3] = fmaf(q3[j], kv, s[3]);
        }

        float p[4];
        #pragma unroll
        for (int i = 0; i < 4; i++) {
            float si = s[i];
            if (kg > qr0 + i) si = -1e30f;

            float mt = si;
            #pragma unroll
            for (int off = 16; off > 0; off >>= 1)
                mt = fmaxf(mt, __shfl_xor_sync(0xffffffffu, mt, off));
            float m_new = fmaxf(m[i], mt);
            p[i] = __expf(si - m_new);
            float alpha = __expf(m[i] - m_new);
            m[i] = m_new;

            float ps = p[i];
            #pragma unroll
            for (int off = 16; off > 0; off >>= 1)
                ps += __shfl_xor_sync(0xffffffffu, ps, off);
            l[i] = l[i] * alpha + ps;
            ov[i] *= alpha;
        }

        #pragma unroll
        for (int k = 0; k < 32; k++) {
            float v = Vs[k][lane];
            float pk0 = __shfl_sync(0xffffffffu, p[0], k);
            float pk1 = __shfl_sync(0xffffffffu, p[1], k);
            float pk2 = __shfl_sync(0xffffffffu, p[2], k);
            float pk3 = __shfl_sync(0xffffffffu, p[3], k);
            ov[0] = fmaf(pk0, v, ov[0]);
            ov[1] = fmaf(pk1, v, ov[1]);
            ov[2] = fmaf(pk2, v, ov[2]);
            ov[3] = fmaf(pk3, v, ov[3]);
        }
    }

    const int j   = h * 32 + lane;
    const int pos = (j & ~7) + k8pos(j & 7);
    #pragma unroll
    for (int i = 0; i < 4; i++) {
        float r = f2tf32f(ov[i] / l[i]);
        out[(size_t)(b * SEQT + qr0 + i) * NATT + pos] = r;
    }
}

// ---------------------------------------------------------------------------
extern "C" void kernel_launch(void* const* d_in, const int* in_sizes, int n_in,
                              void* d_out, int out_size) {
    const float* x  = (const float*)d_in[0];
    const float* W1 = (const float*)d_in[1];
    const float* b1 = (const float*)d_in[2];
    const float* W2 = (const float*)d_in[3];
    const float* b2 = (const float*)d_in[4];
    float* out = (float*)d_out;

    float *qkv, *att, *xr, *w1p, *w2p, *b1p, *part;
    cudaGetSymbolAddress((void**)&qkv, g_qkv);
    cudaGetSymbolAddress((void**)&att, g_att);
    cudaGetSymbolAddress((void**)&xr,  g_xr);
    cudaGetSymbolAddress((void**)&w1p, g_w1p);
    cudaGetSymbolAddress((void**)&w2p, g_w2p);
    cudaGetSymbolAddress((void**)&b1p, g_b1p);
    cudaGetSymbolAddress((void**)&part, g_part);

    cudaFuncSetAttribute(tf32_gemm, cudaFuncAttributeMaxDynamicSharedMemorySize, GEMM_SMEM);

    const int M = NB * SEQT;   // 2048

    {
        int n8 = (M * DIMX) / 8;
        round_perm<<<(n8 + 255) / 256, 256>>>(x, xr, n8);
        int n1 = NQKV * (DIMX / 8);
        prep_w1<<<(n1 + 255) / 256, 256>>>(W1, b1, w1p, b1p);
        int n2 = DIMX * (NATT / 8);
        prep_w2<<<(n2 + 255) / 256, 256>>>(W2, w2p);
    }

    dim3 g1(NQKV / 128, M / 128, KSPLIT);
    tf32_gemm<<<g1, 128, GEMM_SMEM>>>(xr, w1p, nullptr, part, NQKV, DIMX);

    {
        int n4 = (M * NQKV) / 4;
        reduce_k<<<(n4 + 255) / 256, 256>>>(part, b1p, qkv, n4, M * NQKV);
    }

    dim3 g2(SEQT / 32, NHEADS, NB);
    attn_kernel<<<g2, 256>>>(qkv, att);

    dim3 g3(DIMX / 128, M / 128, 1);
    tf32_gemm<<<g3, 128, GEMM_SMEM>>>(att, w2p, b2, out, DIMX, NATT);
}

// round 17
// speedup vs baseline: 1.6343x; 1.6343x over previous
#include <cuda_runtime.h>
#include <cuda_bf16.h>
#include <cstdint>
#include <math.h>

#define DIMX 4096
#define SEQT 1024
#define NB 2
#define NHEADS 32
#define HD 128
#define NQKV 3072
#define NATT 1024
#define KSPLIT 3

__device__ float g_qkv[(size_t)NB * SEQT * NQKV];
__device__ float g_att[(size_t)NB * SEQT * NATT];
__device__ float g_xr [(size_t)NB * SEQT * DIMX];
__device__ float g_w1p[(size_t)NQKV * DIMX];
__device__ float g_w2p[(size_t)DIMX * NATT];
__device__ float g_b1p[NQKV];
__device__ float g_part[(size_t)KSPLIT * NB * SEQT * NQKV];

// ---------------------------------------------------------------------------
__device__ __forceinline__ uint32_t smem_u32(const void* p) {
    uint32_t a;
    asm("{ .reg .u64 t; cvta.to.shared.u64 t, %1; cvt.u32.u64 %0, t; }" : "=r"(a) : "l"(p));
    return a;
}
__device__ __forceinline__ float f2tf32f(float f) {
    uint32_t u;
    asm("cvt.rna.tf32.f32 %0, %1;" : "=r"(u) : "f"(f));
    return __uint_as_float(u);
}
__device__ __forceinline__ void cp16(uint32_t dst, const void* src) {
    asm volatile("cp.async.cg.shared.global [%0], [%1], 16;" :: "r"(dst), "l"(src));
}
#define CP_COMMIT() asm volatile("cp.async.commit_group;" ::: "memory")
#define CP_WAIT(n)  asm volatile("cp.async.wait_group %0;" :: "n"(n) : "memory")

__device__ __forceinline__ void mma_tf32(float* d, const uint32_t* a, const uint32_t* b) {
    asm volatile(
        "mma.sync.aligned.m16n8k8.row.col.f32.tf32.tf32.f32 "
        "{%0,%1,%2,%3}, {%4,%5,%6,%7}, {%8,%9}, {%0,%1,%2,%3};"
        : "+f"(d[0]), "+f"(d[1]), "+f"(d[2]), "+f"(d[3])
        : "r"(a[0]), "r"(a[1]), "r"(a[2]), "r"(a[3]), "r"(b[0]), "r"(b[1]));
}

__device__ __forceinline__ int k8pos(int c) { return (c < 4) ? 2 * c : 2 * (c - 4) + 1; }

// ---------------------------------------------------------------------------
__global__ void round_perm(const float* __restrict__ in, float* __restrict__ out, int n8) {
    int i = blockIdx.x * blockDim.x + threadIdx.x;
    if (i < n8) {
        float4 a = ((const float4*)in)[2 * i];
        float4 b = ((const float4*)in)[2 * i + 1];
        float4 o0, o1;
        o0.x = f2tf32f(a.x); o0.y = f2tf32f(b.x);
        o0.z = f2tf32f(a.y); o0.w = f2tf32f(b.y);
        o1.x = f2tf32f(a.z); o1.y = f2tf32f(b.z);
        o1.z = f2tf32f(a.w); o1.w = f2tf32f(b.w);
        ((float4*)out)[2 * i]     = o0;
        ((float4*)out)[2 * i + 1] = o1;
    }
}

// ---------------------------------------------------------------------------
__global__ void prep_w1(const float* __restrict__ W1, const float* __restrict__ b1,
                        float* __restrict__ W1p, float* __restrict__ b1p) {
    const float scale = 0.08838834764831845f;
    int idx = blockIdx.x * blockDim.x + threadIdx.x;
    if (idx >= NQKV * (DIMX / 8)) return;
    int row = idx / (DIMX / 8);
    int grp = idx % (DIMX / 8);

    float v[8];
    if (row < 1024) {
        const float* s0 = W1 + (size_t)(4 * row) * DIMX + grp * 8;
        #pragma unroll
        for (int c = 0; c < 8; c++)
            v[c] = scale * (s0[c] + s0[DIMX + c] + s0[2 * DIMX + c] + s0[3 * DIMX + c]);
        if (grp == 0)
            b1p[row] = scale * (b1[4 * row] + b1[4 * row + 1] + b1[4 * row + 2] + b1[4 * row + 3]);
    } else {
        int src = (row < 2048) ? (4096 + row - 1024) : (5120 + row - 2048);
        const float* s0 = W1 + (size_t)src * DIMX + grp * 8;
        #pragma unroll
        for (int c = 0; c < 8; c++) v[c] = s0[c];
        if (grp == 0) b1p[row] = b1[src];
    }
    float* o = W1p + (size_t)row * DIMX + grp * 8;
    #pragma unroll
    for (int c = 0; c < 8; c++) o[k8pos(c)] = f2tf32f(v[c]);
}

// ---------------------------------------------------------------------------
__global__ void prep_w2(const float* __restrict__ W2, float* __restrict__ W2p) {
    int idx = blockIdx.x * blockDim.x + threadIdx.x;
    if (idx >= DIMX * (NATT / 8)) return;
    int n   = idx / (NATT / 8);
    int grp = idx % (NATT / 8);
    const float* s0 = W2 + (size_t)n * DIMX + grp * 32;
    float* o = W2p + (size_t)n * NATT + grp * 8;
    #pragma unroll
    for (int c = 0; c < 8; c++) {
        float v = s0[4 * c] + s0[4 * c + 1] + s0[4 * c + 2] + s0[4 * c + 3];
        o[k8pos(c)] = f2tf32f(v);
    }
}

// ---------------------------------------------------------------------------
__global__ void reduce_k(const float* __restrict__ part, const float* __restrict__ bias,
                         float* __restrict__ out, int n4, int stride_elems) {
    int i = blockIdx.x * blockDim.x + threadIdx.x;
    if (i >= n4) return;
    float4 p0 = ((const float4*)part)[i];
    float4 p1 = ((const float4*)(part + (size_t)stride_elems))[i];
    float4 p2 = ((const float4*)(part + 2 * (size_t)stride_elems))[i];
    int col = (i * 4) % NQKV;
    float4 bv = *(const float4*)(bias + col);
    float4 o;
    o.x = (p0.x + p1.x + p2.x) + bv.x;
    o.y = (p0.y + p1.y + p2.y) + bv.y;
    o.z = (p0.z + p1.z + p2.z) + bv.z;
    o.w = (p0.w + p1.w + p2.w) + bv.w;
    ((float4*)out)[i] = o;
}

// ---------------------------------------------------------------------------
// tf32 mma.sync GEMM (R14 verbatim) with split-K via blockIdx.z.
// ---------------------------------------------------------------------------
#define APAD 40
#define TILE_F (128 * APAD)
#define STAGE_F (2 * TILE_F)
#define GEMM_SMEM (2 * STAGE_F * 4)        // 81920 B

__global__ __launch_bounds__(128, 2)
void tf32_gemm(const float* __restrict__ A, const float* __restrict__ W,
               const float* __restrict__ bias, float* __restrict__ C,
               int N, int K) {
    extern __shared__ float sm[];

    const int tid  = threadIdx.x;
    const int wid  = tid / 32;
    const int lane = tid % 32;
    const int wm   = wid >> 1;
    const int wn   = wid & 1;
    const int g    = lane >> 2;
    const int t    = lane & 3;
    const int bx   = blockIdx.x;
    const int by   = blockIdx.y;
    const int bz   = blockIdx.z;

    const int ktot  = K / 32;
    const int kper  = (ktot + (int)gridDim.z - 1) / (int)gridDim.z;
    const int kbeg  = bz * kper;
    const int ntiles = min(kper, ktot - kbeg);

    float* Cz = C + (size_t)bz * (size_t)(gridDim.y * 128) * N;

    const float* Ab = A + (size_t)(by * 128) * K + (size_t)kbeg * 32;
    const float* Wb = W + (size_t)(bx * 128) * K + (size_t)kbeg * 32;

    float acc[4][8][4];
    #pragma unroll
    for (int i = 0; i < 4; i++)
        #pragma unroll
        for (int j = 0; j < 8; j++)
            #pragma unroll
            for (int c = 0; c < 4; c++) acc[i][j][c] = 0.0f;

    const int crow = tid >> 3;
    const int ckc  = (tid & 7) * 4;

    auto load_tile = [&](int buf, int kt) {
        float* as = sm + buf * STAGE_F;
        float* bs = as + TILE_F;
        uint32_t as_u = smem_u32(as);
        uint32_t bs_u = smem_u32(bs);
        const float* Asrc = Ab + kt * 32;
        const float* Bsrc = Wb + kt * 32;
        #pragma unroll
        for (int i = 0; i < 8; i++) {
            int row = crow + i * 16;
            uint32_t doff = (uint32_t)(row * APAD + ckc) * 4u;
            cp16(as_u + doff, Asrc + (size_t)row * K + ckc);
            cp16(bs_u + doff, Bsrc + (size_t)row * K + ckc);
        }
        CP_COMMIT();
    };

    load_tile(0, 0);
    if (ntiles > 1) load_tile(1, 1);

    for (int kt = 0; kt < ntiles; kt++) {
        CP_WAIT(1);
        __syncthreads();

        const int buf = kt & 1;
        const float* as = sm + buf * STAGE_F + (wm * 64) * APAD;
        const float* bs = sm + buf * STAGE_F + TILE_F + (wn * 64) * APAD;

        #pragma unroll
        for (int ks = 0; ks < 4; ks++) {
            const int k0 = ks * 8 + 2 * t;
            uint32_t af[4][4], bf[8][2];
            #pragma unroll
            for (int mt = 0; mt < 4; mt++) {
                float2 lo = *(const float2*)(as + (mt * 16 + g) * APAD + k0);
                float2 hi = *(const float2*)(as + (mt * 16 + g + 8) * APAD + k0);
                af[mt][0] = __float_as_uint(lo.x);
                af[mt][1] = __float_as_uint(hi.x);
                af[mt][2] = __float_as_uint(lo.y);
                af[mt][3] = __float_as_uint(hi.y);
            }
            #pragma unroll
            for (int nt = 0; nt < 8; nt++) {
                float2 bb = *(const float2*)(bs + (nt * 8 + g) * APAD + k0);
                bf[nt][0] = __float_as_uint(bb.x);
                bf[nt][1] = __float_as_uint(bb.y);
            }
            #pragma unroll
            for (int mt = 0; mt < 4; mt++)
                #pragma unroll
                for (int nt = 0; nt < 8; nt++)
                    mma_tf32(acc[mt][nt], af[mt], bf[nt]);
        }

        __syncthreads();
        if (kt + 2 < ntiles)
            load_tile(buf, kt + 2);
    }

    #pragma unroll
    for (int nt = 0; nt < 8; nt++) {
        const int col = bx * 128 + wn * 64 + nt * 8 + 2 * t;
        float2 bv = bias ? *(const float2*)(bias + col) : make_float2(0.f, 0.f);
        #pragma unroll
        for (int mt = 0; mt < 4; mt++) {
            const int row = by * 128 + wm * 64 + mt * 16 + g;
            float2 r0, r1;
            r0.x = acc[mt][nt][0] + bv.x;
            r0.y = acc[mt][nt][1] + bv.y;
            r1.x = acc[mt][nt][2] + bv.x;
            r1.y = acc[mt][nt][3] + bv.y;
            *(float2*)(Cz + (size_t)row * N + col)       = r0;
            *(float2*)(Cz + (size_t)(row + 8) * N + col) = r1;
        }
    }
}

// ---------------------------------------------------------------------------
// Flash attention: 64-row q-tiles (8 rows/warp), double-buffered K/V.
// Per-row accumulator chains are BIT-IDENTICAL to R14 (extra fully-masked
// tiles for lower rows are exact no-ops: alpha=1, p=0).
//   K: LDG->regs prefetch (issued before compute), STS after compute.
//   V: cp.async into alternate buffer during compute.
// ---------------------------------------------------------------------------
__global__ __launch_bounds__(256, 2)
void attn_kernel(const float* __restrict__ qkv, float* __restrict__ out) {
    __shared__ float Qs[64][32];
    __shared__ float Kt[2][32][33];
    __shared__ float Vs[2][32][32];

    const int qt   = blockIdx.x;       // 64-row q tile
    const int h    = blockIdx.y;
    const int b    = blockIdx.z;
    const int tid  = threadIdx.x;
    const int wid  = tid / 32;
    const int lane = tid % 32;

    const float* base = qkv + (size_t)b * SEQT * NQKV;

    #pragma unroll
    for (int it = 0; it < 8; it++) {
        int r = it * 8 + wid;
        Qs[r][lane] = base[(size_t)(qt * 64 + r) * NQKV + h * 32 + lane];
    }

    float ov[8], m[8], l[8];
    #pragma unroll
    for (int i = 0; i < 8; i++) { ov[i] = 0.f; m[i] = -1e30f; l[i] = 0.f; }
    const int qr0 = qt * 64 + wid * 8;

    const int ntiles = 2 * qt + 2;     // 32-row kv tiles

    // loader lane mapping: r = tid/8 (0..31), c4 = (tid%8)*4
    const int lr  = tid / 8;
    const int lc4 = (tid % 8) * 4;
    const uint32_t vs_u = smem_u32(&Vs[0][0][0]);

    // preload tile 0
    float4 kreg;
    {
        const float* rowp = base + (size_t)lr * NQKV + 1024 + h * 32 + lc4;
        kreg = *(const float4*)(rowp);
        cp16(vs_u + (uint32_t)(lr * 32 + lc4) * 4u, rowp + 1024);
        CP_COMMIT();
        Kt[0][lc4 + 0][lr] = kreg.x; Kt[0][lc4 + 1][lr] = kreg.y;
        Kt[0][lc4 + 2][lr] = kreg.z; Kt[0][lc4 + 3][lr] = kreg.w;
    }
    CP_WAIT(0);
    __syncthreads();

    for (int tt = 0; tt < ntiles; tt++) {
        const int buf = tt & 1;
        const int nbuf = buf ^ 1;

        // prefetch tile tt+1: K to regs (latency hidden by compute), V cp.async
        const bool pf = (tt + 1 < ntiles);
        if (pf) {
            const float* rowp = base + (size_t)((tt + 1) * 32 + lr) * NQKV + 1024 + h * 32 + lc4;
            kreg = *(const float4*)(rowp);
            cp16(vs_u + (uint32_t)((nbuf * 32 + lr) * 32 + lc4) * 4u, rowp + 1024);
            CP_COMMIT();
        }

        const int kg = tt * 32 + lane;

        // scores, j outer (R14 arithmetic per row)
        float s[8];
        #pragma unroll
        for (int i = 0; i < 8; i++) s[i] = 0.f;
        #pragma unroll
        for (int j = 0; j < 32; j++) {
            float kv = Kt[buf][j][lane];
            #pragma unroll
            for (int i = 0; i < 8; i++)
                s[i] = fmaf(Qs[wid * 8 + i][j], kv, s[i]);
        }

        // softmax per row (R14 arithmetic)
        float p[8];
        #pragma unroll
        for (int i = 0; i < 8; i++) {
            float si = s[i];
            if (kg > qr0 + i) si = -1e30f;

            float mt = si;
            #pragma unroll
            for (int off = 16; off > 0; off >>= 1)
                mt = fmaxf(mt, __shfl_xor_sync(0xffffffffu, mt, off));
            float m_new = fmaxf(m[i], mt);
            p[i] = __expf(si - m_new);
            float alpha = __expf(m[i] - m_new);
            m[i] = m_new;

            float ps = p[i];
            #pragma unroll
            for (int off = 16; off > 0; off >>= 1)
                ps += __shfl_xor_sync(0xffffffffu, ps, off);
            l[i] = l[i] * alpha + ps;
            ov[i] *= alpha;
        }

        // PV, k outer (R14 arithmetic)
        #pragma unroll
        for (int k = 0; k < 32; k++) {
            float v = Vs[buf][k][lane];
            #pragma unroll
            for (int i = 0; i < 8; i++) {
                float pk = __shfl_sync(0xffffffffu, p[i], k);
                ov[i] = fmaf(pk, v, ov[i]);
            }
        }

        __syncthreads();     // all warps done reading Kt[buf]/Vs[buf]
        if (pf) {
            Kt[nbuf][lc4 + 0][lr] = kreg.x; Kt[nbuf][lc4 + 1][lr] = kreg.y;
            Kt[nbuf][lc4 + 2][lr] = kreg.z; Kt[nbuf][lc4 + 3][lr] = kreg.w;
            CP_WAIT(0);
            __syncthreads(); // next tile's K/V published
        }
    }

    const int j   = h * 32 + lane;
    const int pos = (j & ~7) + k8pos(j & 7);
    #pragma unroll
    for (int i = 0; i < 8; i++) {
        float r = f2tf32f(ov[i] / l[i]);
        out[(size_t)(b * SEQT + qr0 + i) * NATT + pos] = r;
    }
}

// ---------------------------------------------------------------------------
extern "C" void kernel_launch(void* const* d_in, const int* in_sizes, int n_in,
                              void* d_out, int out_size) {
    const float* x  = (const float*)d_in[0];
    const float* W1 = (const float*)d_in[1];
    const float* b1 = (const float*)d_in[2];
    const float* W2 = (const float*)d_in[3];
    const float* b2 = (const float*)d_in[4];
    float* out = (float*)d_out;

    float *qkv, *att, *xr, *w1p, *w2p, *b1p, *part;
    cudaGetSymbolAddress((void**)&qkv, g_qkv);
    cudaGetSymbolAddress((void**)&att, g_att);
    cudaGetSymbolAddress((void**)&xr,  g_xr);
    cudaGetSymbolAddress((void**)&w1p, g_w1p);
    cudaGetSymbolAddress((void**)&w2p, g_w2p);
    cudaGetSymbolAddress((void**)&b1p, g_b1p);
    cudaGetSymbolAddress((void**)&part, g_part);

    cudaFuncSetAttribute(tf32_gemm, cudaFuncAttributeMaxDynamicSharedMemorySize, GEMM_SMEM);

    const int M = NB * SEQT;   // 2048

    {
        int n8 = (M * DIMX) / 8;
        round_perm<<<(n8 + 255) / 256, 256>>>(x, xr, n8);
        int n1 = NQKV * (DIMX / 8);
        prep_w1<<<(n1 + 255) / 256, 256>>>(W1, b1, w1p, b1p);
        int n2 = DIMX * (NATT / 8);
        prep_w2<<<(n2 + 255) / 256, 256>>>(W2, w2p);
    }

    dim3 g1(NQKV / 128, M / 128, KSPLIT);
    tf32_gemm<<<g1, 128, GEMM_SMEM>>>(xr, w1p, nullptr, part, NQKV, DIMX);

    {
        int n4 = (M * NQKV) / 4;
        reduce_k<<<(n4 + 255) / 256, 256>>>(part, b1p, qkv, n4, M * NQKV);
    }

    dim3 g2(SEQT / 64, NHEADS, NB);
    attn_kernel<<<g2, 256>>>(qkv, att);

    dim3 g3(DIMX / 128, M / 128, 1);
    tf32_gemm<<<g3, 128, GEMM_SMEM>>>(att, w2p, b2, out, DIMX, NATT);
}